// round 9
// baseline (speedup 1.0000x reference)
#include <cuda_runtime.h>
#include <cuda_bf16.h>
#include <cstdint>

// Per-qubit accumulated unitaries: [set][qubit][U00,U01,U10,U11] (complex as float2)
__device__ float2 g_U[3][12][4];

__device__ __forceinline__ float2 cmul(float2 a, float2 b) {
    return make_float2(a.x * b.x - a.y * b.y, a.x * b.y + a.y * b.x);
}
__device__ __forceinline__ float2 cadd(float2 a, float2 b) {
    return make_float2(a.x + b.x, a.y + b.y);
}

// 36 threads: thread (w, q) accumulates U <- Ul @ U over layers.
// Ul = Rz(p2) Ry(p1) Rz(p0), p_i = theta_i/2
//    = [[c1 e^{-i(p0+p2)}, -s1 e^{+i(p0-p2)}],
//       [s1 e^{-i(p0-p2)},  c1 e^{+i(p0+p2)}]]
__global__ void unitary_setup_kernel(const float* __restrict__ tQ,
                                     const float* __restrict__ tK,
                                     const float* __restrict__ tV,
                                     int n_layers) {
    int t = threadIdx.x;
    if (t >= 36) return;
    int w = t / 12;
    int q = t % 12;
    const float* th = (w == 0) ? tQ : (w == 1) ? tK : tV;

    float2 U00 = {1.f, 0.f}, U01 = {0.f, 0.f};
    float2 U10 = {0.f, 0.f}, U11 = {1.f, 0.f};
    for (int l = 0; l < n_layers; ++l) {
        const float* tl = th + (l * 12 + q) * 3;
        float p0 = 0.5f * tl[0];
        float p1 = 0.5f * tl[1];
        float p2 = 0.5f * tl[2];
        float c1, s1, ca, sa, cb, sb;
        sincosf(p1, &s1, &c1);
        sincosf(p0 + p2, &sa, &ca);
        sincosf(p0 - p2, &sb, &cb);
        float2 A00 = { c1 * ca, -c1 * sa};
        float2 A01 = {-s1 * cb, -s1 * sb};
        float2 A10 = { s1 * cb, -s1 * sb};
        float2 A11 = { c1 * ca,  c1 * sa};
        float2 n00 = cadd(cmul(A00, U00), cmul(A01, U10));
        float2 n01 = cadd(cmul(A00, U01), cmul(A01, U11));
        float2 n10 = cadd(cmul(A10, U00), cmul(A11, U10));
        float2 n11 = cadd(cmul(A10, U01), cmul(A11, U11));
        U00 = n00; U01 = n01; U10 = n10; U11 = n11;
    }
    g_U[w][q][0] = U00;
    g_U[w][q][1] = U01;
    g_U[w][q][2] = U10;
    g_U[w][q][3] = U11;
}

// Warp-autonomous: global warp g produces item g = w*BS + bs (4096 fp32 = 16 KB).
// Qubit q occupies bit (11-q) of the state index.
// state[i] = Re( L[i>>6] * R[i&63] ); L over qubits 0..5, R over qubits 6..11.
// No shared memory, no __syncthreads — all cross-lane traffic via shfl.
__global__ __launch_bounds__(256, 5)
void vqc_warp_kernel(const float* __restrict__ angles,
                     float* __restrict__ out, int BS) {
    const unsigned FULL = 0xFFFFFFFFu;
    const int g  = blockIdx.x * 8 + (threadIdx.x >> 5);   // item id
    const int ln = threadIdx.x & 31;
    const int w  = g / BS;
    const int bs = g - w * BS;

    // ---------- Phase A: lanes 0..11 apply U[w][q] to [cos(a/2), sin(a/2)] ----------
    float2 v0 = {0.f, 0.f}, v1 = {0.f, 0.f};
    if (ln < 12) {
        const float4* Up = reinterpret_cast<const float4*>(&g_U[w][ln][0]);
        float4 u0 = Up[0];   // U00.x U00.y U01.x U01.y
        float4 u1 = Up[1];   // U10.x U10.y U11.x U11.y
        float a = angles[bs * 12 + ln];
        float c, s;
        sincosf(0.5f * a, &s, &c);
        v0 = make_float2(u0.x * c + u0.z * s, u0.y * c + u0.w * s);
        v1 = make_float2(u1.x * c + u1.z * s, u1.y * c + u1.w * s);
    }

    // ---------- Phase B: distributed partial products via shfl ----------
    // Lane ln holds L[ln], L[ln+32], R[ln], R[ln+32].
    float2 L0, L1, R0, R1;
    {
        float2 a0[6], a1[6];
        // L over qubits 0..5
        #pragma unroll
        for (int j = 0; j < 6; ++j) {
            a0[j].x = __shfl_sync(FULL, v0.x, j);
            a0[j].y = __shfl_sync(FULL, v0.y, j);
            a1[j].x = __shfl_sync(FULL, v1.x, j);
            a1[j].y = __shfl_sync(FULL, v1.y, j);
        }
        #pragma unroll
        for (int hh = 0; hh < 2; ++hh) {
            int h = ln + hh * 32;
            float2 p = ((h >> 5) & 1) ? a1[0] : a0[0];
            #pragma unroll
            for (int j = 1; j < 6; ++j)
                p = cmul(p, ((h >> (5 - j)) & 1) ? a1[j] : a0[j]);
            if (hh == 0) L0 = p; else L1 = p;
        }
        // R over qubits 6..11
        #pragma unroll
        for (int j = 0; j < 6; ++j) {
            a0[j].x = __shfl_sync(FULL, v0.x, 6 + j);
            a0[j].y = __shfl_sync(FULL, v0.y, 6 + j);
            a1[j].x = __shfl_sync(FULL, v1.x, 6 + j);
            a1[j].y = __shfl_sync(FULL, v1.y, 6 + j);
        }
        #pragma unroll
        for (int hh = 0; hh < 2; ++hh) {
            int h = ln + hh * 32;
            float2 p = ((h >> 5) & 1) ? a1[0] : a0[0];
            #pragma unroll
            for (int j = 1; j < 6; ++j)
                p = cmul(p, ((h >> (5 - j)) & 1) ? a1[j] : a0[j]);
            if (hh == 0) R0 = p; else R1 = p;
        }
    }

    // ---------- Phase C: stores ----------
    // Lane ln's float4 quad covers R indices lo..lo+3 (invariant across iterations):
    //   lo = ((it*32+ln)*4) & 63 = (ln*4) & 63
    const int lo  = (ln << 2) & 63;
    const int sel = lo >> 5;
    const int sb  = lo & 31;
    float2 rq[4];
    #pragma unroll
    for (int k = 0; k < 4; ++k) {
        float x0 = __shfl_sync(FULL, R0.x, sb + k);
        float x1 = __shfl_sync(FULL, R1.x, sb + k);
        float y0 = __shfl_sync(FULL, R0.y, sb + k);
        float y1 = __shfl_sync(FULL, R1.y, sb + k);
        rq[k].x = sel ? x1 : x0;
        rq[k].y = sel ? y1 : y0;
    }

    float4* o4 = reinterpret_cast<float4*>(out + (size_t)g * 4096);
    const int lhi = ln >> 4;   // 0/1: which of the two L indices this half-warp uses
    #pragma unroll
    for (int it = 0; it < 32; ++it) {
        int idx = it * 2 + lhi;            // L index 0..63
        float Lx, Ly;
        if (it < 16) {
            Lx = __shfl_sync(FULL, L0.x, idx);
            Ly = __shfl_sync(FULL, L0.y, idx);
        } else {
            Lx = __shfl_sync(FULL, L1.x, idx - 32);
            Ly = __shfl_sync(FULL, L1.y, idx - 32);
        }
        float4 r;
        r.x = Lx * rq[0].x - Ly * rq[0].y;
        r.y = Lx * rq[1].x - Ly * rq[1].y;
        r.z = Lx * rq[2].x - Ly * rq[2].y;
        r.w = Lx * rq[3].x - Ly * rq[3].y;
        o4[it * 32 + ln] = r;
    }
}

extern "C" void kernel_launch(void* const* d_in, const int* in_sizes, int n_in,
                              void* d_out, int out_size) {
    const float* angles = (const float*)d_in[0];
    const float* tQ     = (const float*)d_in[1];
    const float* tK     = (const float*)d_in[2];
    const float* tV     = (const float*)d_in[3];
    float* out          = (float*)d_out;

    const int NQ = 12;
    const int BS = in_sizes[0] / NQ;          // B*S = 4096
    const int L  = in_sizes[1] / (NQ * 3);    // 4 layers

    unitary_setup_kernel<<<1, 64>>>(tQ, tK, tV, L);

    const int n_items = 3 * BS;               // 12288 warp-items
    vqc_warp_kernel<<<n_items / 8, 256>>>(angles, out, BS);
}

// round 11
// speedup vs baseline: 1.0793x; 1.0793x over previous
#include <cuda_runtime.h>
#include <cuda_bf16.h>
#include <cstdint>

__device__ __forceinline__ float2 cmul(float2 a, float2 b) {
    return make_float2(a.x * b.x - a.y * b.y, a.x * b.y + a.y * b.x);
}
__device__ __forceinline__ float2 cadd(float2 a, float2 b) {
    return make_float2(a.x + b.x, a.y + b.y);
}

// Warp-autonomous, fully fused: global warp g produces item g = w*BS + bs
// (4096 fp32 = 16 KB). Qubit q occupies bit (11-q) of the state index.
// state[i] = Re( L[i>>6] * R[i&63] ); L over qubits 0..5, R over qubits 6..11.
// No shared memory, no __syncthreads — all cross-lane traffic via shfl.
//
// Phase A is layer-parallel: lane 2q+p accumulates half the layers of qubit q's
// unitary; a shfl_xor(1) partner exchange + one complex 2x2 matmul completes
// U = U_hi @ U_lo on even lanes. Phase B then broadcasts from even lanes.
__global__ __launch_bounds__(128, 10)
void vqc_warp_kernel(const float* __restrict__ angles,
                     const float* __restrict__ tQ,
                     const float* __restrict__ tK,
                     const float* __restrict__ tV,
                     float* __restrict__ out,
                     int BS, int n_layers) {
    const unsigned FULL = 0xFFFFFFFFu;
    const int g  = blockIdx.x * 4 + (threadIdx.x >> 5);   // item id
    const int ln = threadIdx.x & 31;
    const int w  = g / BS;
    const int bs = g - w * BS;

    // ---------- Phase A: layer-split unitary accumulation ----------
    // Ul = Rz(p2) Ry(p1) Rz(p0), p_i = theta_i/2
    //    = [[c1 e^{-i(p0+p2)}, -s1 e^{+i(p0-p2)}],
    //       [s1 e^{-i(p0-p2)},  c1 e^{+i(p0+p2)}]]
    float2 U00 = {1.f, 0.f}, U01 = {0.f, 0.f};
    float2 U10 = {0.f, 0.f}, U11 = {1.f, 0.f};
    const int q2  = ln >> 1;    // qubit (valid for ln < 24)
    const int par = ln & 1;     // 0: layers [0, n0)   1: layers [n0, L)
    if (ln < 24) {
        const float* th = (w == 0) ? tQ : (w == 1) ? tK : tV;
        const int n0   = (n_layers + 1) >> 1;
        const int lbeg = par ? n0 : 0;
        const int lend = par ? n_layers : n0;
        for (int l = lbeg; l < lend; ++l) {
            const float* tl = th + (l * 12 + q2) * 3;
            float p0 = 0.5f * tl[0];
            float p1 = 0.5f * tl[1];
            float p2 = 0.5f * tl[2];
            float c1, s1, ca, sa, cb, sb;
            sincosf(p1, &s1, &c1);
            sincosf(p0 + p2, &sa, &ca);
            sincosf(p0 - p2, &sb, &cb);
            float2 A00 = { c1 * ca, -c1 * sa};
            float2 A01 = {-s1 * cb, -s1 * sb};
            float2 A10 = { s1 * cb, -s1 * sb};
            float2 A11 = { c1 * ca,  c1 * sa};
            float2 n00 = cadd(cmul(A00, U00), cmul(A01, U10));
            float2 n01 = cadd(cmul(A00, U01), cmul(A01, U11));
            float2 n10 = cadd(cmul(A10, U00), cmul(A11, U10));
            float2 n11 = cadd(cmul(A10, U01), cmul(A11, U11));
            U00 = n00; U01 = n01; U10 = n10; U11 = n11;
        }
    }
    // Partner exchange: even lane gets odd lane's upper-half product.
    float2 P00, P01, P10, P11;
    P00.x = __shfl_xor_sync(FULL, U00.x, 1);  P00.y = __shfl_xor_sync(FULL, U00.y, 1);
    P01.x = __shfl_xor_sync(FULL, U01.x, 1);  P01.y = __shfl_xor_sync(FULL, U01.y, 1);
    P10.x = __shfl_xor_sync(FULL, U10.x, 1);  P10.y = __shfl_xor_sync(FULL, U10.y, 1);
    P11.x = __shfl_xor_sync(FULL, U11.x, 1);  P11.y = __shfl_xor_sync(FULL, U11.y, 1);

    // Even lanes (ln = 2q < 24): full U = P @ U, then apply [cos(a/2), sin(a/2)].
    float2 v0 = {0.f, 0.f}, v1 = {0.f, 0.f};
    if (ln < 24 && par == 0) {
        float2 n00 = cadd(cmul(P00, U00), cmul(P01, U10));
        float2 n01 = cadd(cmul(P00, U01), cmul(P01, U11));
        float2 n10 = cadd(cmul(P10, U00), cmul(P11, U10));
        float2 n11 = cadd(cmul(P10, U01), cmul(P11, U11));
        float a = angles[bs * 12 + q2];
        float c, s;
        sincosf(0.5f * a, &s, &c);
        v0 = make_float2(n00.x * c + n01.x * s, n00.y * c + n01.y * s);
        v1 = make_float2(n10.x * c + n11.x * s, n10.y * c + n11.y * s);
    }

    // ---------- Phase B: distributed partial products via shfl ----------
    // v[q] lives at lane 2q. Lane ln holds L[ln], L[ln+32], R[ln], R[ln+32].
    float2 L0, L1, R0, R1;
    {
        float2 a0[6], a1[6];
        // L over qubits 0..5 (source lanes 0,2,..,10)
        #pragma unroll
        for (int j = 0; j < 6; ++j) {
            a0[j].x = __shfl_sync(FULL, v0.x, 2 * j);
            a0[j].y = __shfl_sync(FULL, v0.y, 2 * j);
            a1[j].x = __shfl_sync(FULL, v1.x, 2 * j);
            a1[j].y = __shfl_sync(FULL, v1.y, 2 * j);
        }
        #pragma unroll
        for (int hh = 0; hh < 2; ++hh) {
            int h = ln + hh * 32;
            float2 p = ((h >> 5) & 1) ? a1[0] : a0[0];
            #pragma unroll
            for (int j = 1; j < 6; ++j)
                p = cmul(p, ((h >> (5 - j)) & 1) ? a1[j] : a0[j]);
            if (hh == 0) L0 = p; else L1 = p;
        }
        // R over qubits 6..11 (source lanes 12,14,..,22)
        #pragma unroll
        for (int j = 0; j < 6; ++j) {
            a0[j].x = __shfl_sync(FULL, v0.x, 2 * (6 + j));
            a0[j].y = __shfl_sync(FULL, v0.y, 2 * (6 + j));
            a1[j].x = __shfl_sync(FULL, v1.x, 2 * (6 + j));
            a1[j].y = __shfl_sync(FULL, v1.y, 2 * (6 + j));
        }
        #pragma unroll
        for (int hh = 0; hh < 2; ++hh) {
            int h = ln + hh * 32;
            float2 p = ((h >> 5) & 1) ? a1[0] : a0[0];
            #pragma unroll
            for (int j = 1; j < 6; ++j)
                p = cmul(p, ((h >> (5 - j)) & 1) ? a1[j] : a0[j]);
            if (hh == 0) R0 = p; else R1 = p;
        }
    }

    // ---------- Phase C: stores ----------
    // Lane ln's float4 quad covers R indices lo..lo+3 (invariant across iterations).
    const int lo  = (ln << 2) & 63;
    const int sel = lo >> 5;
    const int sb  = lo & 31;
    float2 rq[4];
    #pragma unroll
    for (int k = 0; k < 4; ++k) {
        float x0 = __shfl_sync(FULL, R0.x, sb + k);
        float x1 = __shfl_sync(FULL, R1.x, sb + k);
        float y0 = __shfl_sync(FULL, R0.y, sb + k);
        float y1 = __shfl_sync(FULL, R1.y, sb + k);
        rq[k].x = sel ? x1 : x0;
        rq[k].y = sel ? y1 : y0;
    }

    float4* o4 = reinterpret_cast<float4*>(out + (size_t)g * 4096);
    const int lhi = ln >> 4;   // 0/1: which of the two L indices this half-warp uses
    #pragma unroll
    for (int it = 0; it < 32; ++it) {
        int idx = it * 2 + lhi;            // L index 0..63
        float Lx, Ly;
        if (it < 16) {
            Lx = __shfl_sync(FULL, L0.x, idx);
            Ly = __shfl_sync(FULL, L0.y, idx);
        } else {
            Lx = __shfl_sync(FULL, L1.x, idx - 32);
            Ly = __shfl_sync(FULL, L1.y, idx - 32);
        }
        float4 r;
        r.x = Lx * rq[0].x - Ly * rq[0].y;
        r.y = Lx * rq[1].x - Ly * rq[1].y;
        r.z = Lx * rq[2].x - Ly * rq[2].y;
        r.w = Lx * rq[3].x - Ly * rq[3].y;
        o4[it * 32 + ln] = r;
    }
}

extern "C" void kernel_launch(void* const* d_in, const int* in_sizes, int n_in,
                              void* d_out, int out_size) {
    const float* angles = (const float*)d_in[0];
    const float* tQ     = (const float*)d_in[1];
    const float* tK     = (const float*)d_in[2];
    const float* tV     = (const float*)d_in[3];
    float* out          = (float*)d_out;

    const int NQ = 12;
    const int BS = in_sizes[0] / NQ;          // B*S = 4096
    const int L  = in_sizes[1] / (NQ * 3);    // 4 layers

    const int n_items = 3 * BS;               // 12288 warp-items
    vqc_warp_kernel<<<n_items / 4, 128>>>(angles, tQ, tK, tV, out, BS, L);
}